// round 12
// baseline (speedup 1.0000x reference)
#include <cuda_runtime.h>
#include <math.h>

#define BB 64
#define QQ 4096
#define NN 256
#define NL 21
#define QCH 64                   // q rows per block
#define KC  6                    // candidate cap per row (overflow -> exact recompute)
#define INF_REPLACE 1000000.0f
// Conservative gate on expanded d^2 = |p|^2 - 2 p.t + |t|^2 (fp32 magnitudes
// <= ~1.5e4 -> rounding error << 1/16). Any pair with true d^2 <= 4 passes the
// gate; gated-in pairs are decided by the exact reference computation
// (dist = sqrt(sum((p-t)^2)) <= 2), so boundary decisions match the reference.
#define THR_FAST 4.0625f

// ---------------- exact cost (reference arithmetic) -------------------------
__device__ __noinline__ float exact_cost(
    const float* __restrict__ logits, const int* __restrict__ labels,
    const float* __restrict__ tboxes,
    int b, int q, int n,
    float pcx, float pcy, float pcz,
    float psx, float psy, float psz, float dist)
{
    const float* tb = tboxes + ((size_t)b * NN + n) * 6;
    const float tcx = __ldg(tb + 0), tcy = __ldg(tb + 1), tcz = __ldg(tb + 2);
    const float tsx = __ldg(tb + 3), tsy = __ldg(tb + 4), tsz = __ldg(tb + 5);

    float ix = fminf(pcx + 0.5f*psx, tcx + 0.5f*tsx) - fmaxf(pcx - 0.5f*psx, tcx - 0.5f*tsx);
    float iy = fminf(pcy + 0.5f*psy, tcy + 0.5f*tsy) - fmaxf(pcy - 0.5f*psy, tcy - 0.5f*tsy);
    float iz = fminf(pcz + 0.5f*psz, tcz + 0.5f*tsz) - fmaxf(pcz - 0.5f*psz, tcz - 0.5f*tsz);
    ix = fmaxf(ix, 0.0f); iy = fmaxf(iy, 0.0f); iz = fmaxf(iz, 0.0f);

    const float inter = ix * iy * iz;
    const float vol1 = psx * psy * psz;
    const float vol2 = tsx * tsy * tsz;
    const float uni  = vol1 + vol2 - inter;
    const float iou  = (uni > 0.0f) ? (inter / uni) : 0.0f;

    const float* lg = logits + ((size_t)b * QQ + q) * NL;
    const int lbl = __ldg(labels + b * NN + n);
    float s = 0.0f, el = 0.0f;
    #pragma unroll
    for (int c = 0; c < NL; c++) {
        const float e = expf(__ldg(lg + c));
        s += e;
        if (c == lbl) el = e;
    }
    const float cls = -(el / s);
    return cls + 5.0f * dist + 2.0f * (1.0f - iou);
}

// ---------------- single fused kernel ---------------------------------------
__global__ __launch_bounds__(256) void matcher_kernel(
    const float* __restrict__ logits,    // [B, Q, 21]
    const float* __restrict__ pboxes,    // [B, Q, 6]
    const int*   __restrict__ labels,    // [B, N]
    const float* __restrict__ tboxes,    // [B, N, 6]
    float*       __restrict__ out)       // [B, Q, N]
{
    const int b  = blockIdx.y;
    const int q0 = blockIdx.x * QCH;
    const int t  = threadIdx.x;

    __shared__ float4 s_tA[NN];          // (-2tx, -2ty, -2tz, |t|^2) gate consts
    __shared__ float  s_pb[QCH * 6];     // this chunk's pred boxes
    __shared__ int    s_cnt[QCH];        // candidates found per row
    __shared__ short  s_cn[QCH][KC];     // candidate target index
    __shared__ float  s_cv[QCH][KC];     // candidate exact value

    // ---- stage (coalesced) ----
    {
        const float* tb = tboxes + (size_t)b * NN * 6;
        __shared__ float s_traw[NN * 6];
        #pragma unroll
        for (int i = t; i < NN * 6; i += 256) s_traw[i] = tb[i];
        const float* pb = pboxes + ((size_t)b * QQ + q0) * 6;
        #pragma unroll
        for (int i = t; i < QCH * 6; i += 256) s_pb[i] = pb[i];
        if (t < QCH) s_cnt[t] = 0;
        __syncthreads();
        const float x = s_traw[t*6+0], y = s_traw[t*6+1], z = s_traw[t*6+2];
        s_tA[t] = make_float4(-2.0f*x, -2.0f*y, -2.0f*z, x*x + y*y + z*z);
        __syncthreads();
    }

    // ---- Phase 1: gate. thread t: row r = t>>2, targets [(t&3)*64, +64) ----
    {
        const int r  = t >> 2;
        const int n0 = (t & 3) * 64;
        const float px = s_pb[r*6+0], py = s_pb[r*6+1], pz = s_pb[r*6+2];
        const float tq = THR_FAST - (px*px + py*py + pz*pz);  // near-maybe iff m <= tq

        #pragma unroll 4
        for (int j = 0; j < 64; j++) {
            const float4 A = s_tA[n0 + j];
            const float m = fmaf(A.x, px, fmaf(A.y, py, fmaf(A.z, pz, A.w)));
            if (m <= tq) {
                // exact decision (reference arithmetic)
                const float tcx = -0.5f * A.x, tcy = -0.5f * A.y, tcz = -0.5f * A.z;
                const float dx = px - tcx, dy = py - tcy, dz = pz - tcz;
                const float dist = sqrtf(dx*dx + dy*dy + dz*dz);
                if (dist <= 2.0f) {
                    const float v = exact_cost(logits, labels, tboxes,
                                               b, q0 + r, n0 + j,
                                               px, py, pz,
                                               s_pb[r*6+3], s_pb[r*6+4], s_pb[r*6+5],
                                               dist);
                    const int slot = atomicAdd(&s_cnt[r], 1);
                    if (slot < KC) { s_cn[r][slot] = (short)(n0 + j); s_cv[r][slot] = v; }
                }
            }
        }
    }
    __syncthreads();

    // ---- Phase 2: coalesced stream. thread t: col quad t&63, row off t>>6 ----
    float4* base4 = (float4*)(out + ((size_t)b * QQ + q0) * NN);
    const int g  = t >> 6;                 // 0..3
    const int c4 = t & 63;                 // targets 4*c4 .. 4*c4+3
    const float4 vinf = make_float4(INF_REPLACE, INF_REPLACE, INF_REPLACE, INF_REPLACE);

    #pragma unroll 4
    for (int k = 0; k < QCH / 4; k++) {
        const int row = (k << 2) + g;      // warp-uniform
        const int cnt = s_cnt[row];        // warp-uniform LDS
        float4 v = vinf;
        if (cnt != 0) {
            if (cnt <= KC) {
                for (int j = 0; j < cnt; j++) {            // warp-uniform loop
                    const int d = (int)s_cn[row][j] - 4 * c4;
                    if ((unsigned)d < 4u) {
                        const float val = s_cv[row][j];
                        if (d == 0) v.x = val; else if (d == 1) v.y = val;
                        else if (d == 2) v.z = val; else v.w = val;
                    }
                }
            } else {
                // overflow fallback: recompute this thread's 4 columns exactly
                const float px = s_pb[row*6+0], py = s_pb[row*6+1], pz = s_pb[row*6+2];
                const float psx = s_pb[row*6+3], psy = s_pb[row*6+4], psz = s_pb[row*6+5];
                const float tq = THR_FAST - (px*px + py*py + pz*pz);
                float rv[4];
                #pragma unroll
                for (int jj = 0; jj < 4; jj++) {
                    rv[jj] = INF_REPLACE;
                    const int n = 4 * c4 + jj;
                    const float4 A = s_tA[n];
                    const float m = fmaf(A.x, px, fmaf(A.y, py, fmaf(A.z, pz, A.w)));
                    if (m <= tq) {
                        const float tcx = -0.5f*A.x, tcy = -0.5f*A.y, tcz = -0.5f*A.z;
                        const float dx = px - tcx, dy = py - tcy, dz = pz - tcz;
                        const float dist = sqrtf(dx*dx + dy*dy + dz*dz);
                        if (dist <= 2.0f)
                            rv[jj] = exact_cost(logits, labels, tboxes,
                                                b, q0 + row, n,
                                                px, py, pz, psx, psy, psz, dist);
                    }
                }
                v = make_float4(rv[0], rv[1], rv[2], rv[3]);
            }
        }
        // row stride = NN/4 = 64 float4s: index = row*64 + c4 = k*256 + g*64 + c4
        base4[(size_t)k * 256 + (size_t)g * 64 + c4] = v;
    }
}

extern "C" void kernel_launch(void* const* d_in, const int* in_sizes, int n_in,
                              void* d_out, int out_size)
{
    const float* logits = (const float*)d_in[0];  // [B,Q,21]
    const float* pboxes = (const float*)d_in[1];  // [B,Q,6]
    const int*   labels = (const int*)  d_in[2];  // [B,N]
    const float* tboxes = (const float*)d_in[3];  // [B,N,6]
    float*       out    = (float*)d_out;          // [B,Q,N]

    dim3 grid(QQ / QCH, BB);                      // (64, 64) = 4096 blocks
    matcher_kernel<<<grid, 256>>>(logits, pboxes, labels, tboxes, out);
}

// round 13
// speedup vs baseline: 2.4472x; 2.4472x over previous
#include <cuda_runtime.h>
#include <math.h>

#define BB 64
#define QQ 4096
#define NN 256
#define NL 21
#define QT  128                  // q rows per block
#define INF_REPLACE 1000000.0f
// Conservative gate on expanded d^2 = |p|^2 - 2 p.t + |t|^2 (fp32 magnitudes
// <= ~1.5e4 -> rounding error << 1/16). Every pair with true d^2 <= 4 passes;
// gated-in pairs are decided by the exact reference computation
// (dist = sqrt(sum((p-t)^2)) <= 2), so boundary decisions match the reference.
#define THR_FAST 4.0625f

// ---------------- exact cost (reference arithmetic, rare) -------------------
__device__ __noinline__ float exact_cost(
    const float* __restrict__ logits, const int* __restrict__ labels,
    const float* __restrict__ tboxes,
    int b, int q, int n,
    float pcx, float pcy, float pcz, float dist,
    const float* __restrict__ pboxes)
{
    const float* pb = pboxes + ((size_t)b * QQ + q) * 6;
    const float psx = __ldg(pb + 3), psy = __ldg(pb + 4), psz = __ldg(pb + 5);

    const float* tb = tboxes + ((size_t)b * NN + n) * 6;
    const float tcx = __ldg(tb + 0), tcy = __ldg(tb + 1), tcz = __ldg(tb + 2);
    const float tsx = __ldg(tb + 3), tsy = __ldg(tb + 4), tsz = __ldg(tb + 5);

    float ix = fminf(pcx + 0.5f*psx, tcx + 0.5f*tsx) - fmaxf(pcx - 0.5f*psx, tcx - 0.5f*tsx);
    float iy = fminf(pcy + 0.5f*psy, tcy + 0.5f*tsy) - fmaxf(pcy - 0.5f*psy, tcy - 0.5f*tsy);
    float iz = fminf(pcz + 0.5f*psz, tcz + 0.5f*tsz) - fmaxf(pcz - 0.5f*psz, tcz - 0.5f*tsz);
    ix = fmaxf(ix, 0.0f); iy = fmaxf(iy, 0.0f); iz = fmaxf(iz, 0.0f);

    const float inter = ix * iy * iz;
    const float vol1 = psx * psy * psz;
    const float vol2 = tsx * tsy * tsz;
    const float uni  = vol1 + vol2 - inter;
    const float iou  = (uni > 0.0f) ? (inter / uni) : 0.0f;

    const float* lg = logits + ((size_t)b * QQ + q) * NL;
    const int lbl = __ldg(labels + b * NN + n);
    float s = 0.0f, el = 0.0f;
    #pragma unroll
    for (int c = 0; c < NL; c++) {
        const float e = expf(__ldg(lg + c));
        s += e;
        if (c == lbl) el = e;
    }
    const float cls = -(el / s);
    return cls + 5.0f * dist + 2.0f * (1.0f - iou);
}

// ---------------- single fused kernel ---------------------------------------
__global__ __launch_bounds__(256) void matcher_kernel(
    const float* __restrict__ logits,    // [B, Q, 21]
    const float* __restrict__ pboxes,    // [B, Q, 6]
    const int*   __restrict__ labels,    // [B, N]
    const float* __restrict__ tboxes,    // [B, N, 6]
    float*       __restrict__ out)       // [B, Q, N]
{
    const int b  = blockIdx.y;
    const int q0 = blockIdx.x * QT;
    const int t  = threadIdx.x;          // t == target index n

    __shared__ float  s_praw[QT * 6];    // staged pred boxes (raw)
    __shared__ float  s_traw[NN * 6];    // staged target boxes (raw)
    __shared__ float4 s_p[QT];           // (px, py, pz, tq = THR - |p|^2)

    // ---- coalesced staging ----
    {
        const float* pb = pboxes + ((size_t)b * QQ + q0) * 6;
        #pragma unroll
        for (int i = t; i < QT * 6; i += 256) s_praw[i] = pb[i];
        const float* tb = tboxes + (size_t)b * NN * 6;
        #pragma unroll
        for (int i = t; i < NN * 6; i += 256) s_traw[i] = tb[i];
    }
    __syncthreads();

    // per-thread target gate constants (registers for the whole block)
    const float tx = s_traw[t*6+0], ty = s_traw[t*6+1], tz = s_traw[t*6+2];
    const float Ax = -2.0f * tx, Ay = -2.0f * ty, Az = -2.0f * tz;
    const float K  = tx*tx + ty*ty + tz*tz;

    // per-row broadcast constants
    if (t < QT) {
        const float x = s_praw[t*6+0], y = s_praw[t*6+1], z = s_praw[t*6+2];
        s_p[t] = make_float4(x, y, z, THR_FAST - (x*x + y*y + z*z));
    }
    __syncthreads();

    // ---- main loop: one row per iteration, broadcast LDS + 3 FFMA gate ----
    float* ocol = out + ((size_t)b * QQ + q0) * NN + t;

    #pragma unroll 4
    for (int r = 0; r < QT; r++) {
        const float4 p = s_p[r];                       // broadcast (conflict-free)
        const float m = fmaf(Ax, p.x, fmaf(Ay, p.y, fmaf(Az, p.z, K)));
        const bool near = (m <= p.w);
        float v = INF_REPLACE;
        if (__any_sync(0xFFFFFFFFu, near)) {           // warp-uniform, rare (~0.9%)
            if (near) {
                // exact decision (reference arithmetic)
                const float dx = p.x - tx, dy = p.y - ty, dz = p.z - tz;
                const float dist = sqrtf(dx*dx + dy*dy + dz*dz);
                if (dist <= 2.0f)
                    v = exact_cost(logits, labels, tboxes,
                                   b, q0 + r, t, p.x, p.y, p.z, dist, pboxes);
            }
        }
        ocol[(size_t)r * NN] = v;
    }
}

extern "C" void kernel_launch(void* const* d_in, const int* in_sizes, int n_in,
                              void* d_out, int out_size)
{
    const float* logits = (const float*)d_in[0];  // [B,Q,21]
    const float* pboxes = (const float*)d_in[1];  // [B,Q,6]
    const int*   labels = (const int*)  d_in[2];  // [B,N]
    const float* tboxes = (const float*)d_in[3];  // [B,N,6]
    float*       out    = (float*)d_out;          // [B,Q,N]

    dim3 grid(QQ / QT, BB);                       // (32, 64) = 2048 blocks
    matcher_kernel<<<grid, 256>>>(logits, pboxes, labels, tboxes, out);
}

// round 14
// speedup vs baseline: 2.4859x; 1.0158x over previous
#include <cuda_runtime.h>
#include <math.h>

#define BB 64
#define QQ 4096
#define NN 256
#define NL 21
#define QT  128                  // q rows per block
#define INF_REPLACE 1000000.0f
// Conservative gate on expanded d^2 = |p|^2 - 2 p.t + |t|^2 (fp32 magnitudes
// <= ~1.5e4 -> rounding error << 1/16). Every pair with true d^2 <= 4 passes;
// gated-in pairs are decided by the exact reference computation
// (dist = sqrt(sum((p-t)^2)) <= 2), so boundary decisions match the reference.
#define THR_FAST 4.0625f

// ---------------- exact cost (reference arithmetic, rare) -------------------
__device__ __noinline__ float exact_cost(
    const float* __restrict__ logits, const int* __restrict__ labels,
    const float* __restrict__ tboxes,
    int b, int q, int n,
    float pcx, float pcy, float pcz, float dist,
    const float* __restrict__ pboxes)
{
    const float* pb = pboxes + ((size_t)b * QQ + q) * 6;
    const float psx = __ldg(pb + 3), psy = __ldg(pb + 4), psz = __ldg(pb + 5);

    const float* tb = tboxes + ((size_t)b * NN + n) * 6;
    const float tcx = __ldg(tb + 0), tcy = __ldg(tb + 1), tcz = __ldg(tb + 2);
    const float tsx = __ldg(tb + 3), tsy = __ldg(tb + 4), tsz = __ldg(tb + 5);

    float ix = fminf(pcx + 0.5f*psx, tcx + 0.5f*tsx) - fmaxf(pcx - 0.5f*psx, tcx - 0.5f*tsx);
    float iy = fminf(pcy + 0.5f*psy, tcy + 0.5f*tsy) - fmaxf(pcy - 0.5f*psy, tcy - 0.5f*tsy);
    float iz = fminf(pcz + 0.5f*psz, tcz + 0.5f*tsz) - fmaxf(pcz - 0.5f*psz, tcz - 0.5f*tsz);
    ix = fmaxf(ix, 0.0f); iy = fmaxf(iy, 0.0f); iz = fmaxf(iz, 0.0f);

    const float inter = ix * iy * iz;
    const float vol1 = psx * psy * psz;
    const float vol2 = tsx * tsy * tsz;
    const float uni  = vol1 + vol2 - inter;
    const float iou  = (uni > 0.0f) ? (inter / uni) : 0.0f;

    const float* lg = logits + ((size_t)b * QQ + q) * NL;
    const int lbl = __ldg(labels + b * NN + n);
    float s = 0.0f, el = 0.0f;
    #pragma unroll
    for (int c = 0; c < NL; c++) {
        const float e = expf(__ldg(lg + c));
        s += e;
        if (c == lbl) el = e;
    }
    const float cls = -(el / s);
    return cls + 5.0f * dist + 2.0f * (1.0f - iou);
}

// ---------------- single fused kernel ---------------------------------------
__global__ __launch_bounds__(256) void matcher_kernel(
    const float* __restrict__ logits,    // [B, Q, 21]
    const float* __restrict__ pboxes,    // [B, Q, 6]
    const int*   __restrict__ labels,    // [B, N]
    const float* __restrict__ tboxes,    // [B, N, 6]
    float*       __restrict__ out)       // [B, Q, N]
{
    const int b  = blockIdx.y;
    const int q0 = blockIdx.x * QT;
    const int t  = threadIdx.x;
    const int g  = t >> 7;               // 0..1 — row offset (warp-uniform)
    const int u  = t & 127;              // target pair index: owns n = 2u, 2u+1

    __shared__ float  s_praw[QT * 6];    // staged pred boxes (raw)
    __shared__ float  s_traw[NN * 6];    // staged target boxes (raw)
    __shared__ float4 s_p[QT];           // (px, py, pz, tq = THR - |p|^2)

    // ---- coalesced staging ----
    {
        const float* pb = pboxes + ((size_t)b * QQ + q0) * 6;
        #pragma unroll
        for (int i = t; i < QT * 6; i += 256) s_praw[i] = pb[i];
        const float* tb = tboxes + (size_t)b * NN * 6;
        #pragma unroll
        for (int i = t; i < NN * 6; i += 256) s_traw[i] = tb[i];
    }
    __syncthreads();

    // per-thread gate constants for the two owned targets (registers)
    const int n0 = 2 * u, n1 = 2 * u + 1;
    const float tx0 = s_traw[n0*6+0], ty0 = s_traw[n0*6+1], tz0 = s_traw[n0*6+2];
    const float tx1 = s_traw[n1*6+0], ty1 = s_traw[n1*6+1], tz1 = s_traw[n1*6+2];
    const float Ax0 = -2.0f*tx0, Ay0 = -2.0f*ty0, Az0 = -2.0f*tz0;
    const float K0  = tx0*tx0 + ty0*ty0 + tz0*tz0;
    const float Ax1 = -2.0f*tx1, Ay1 = -2.0f*ty1, Az1 = -2.0f*tz1;
    const float K1  = tx1*tx1 + ty1*ty1 + tz1*tz1;

    // per-row broadcast constants
    if (t < QT) {
        const float x = s_praw[t*6+0], y = s_praw[t*6+1], z = s_praw[t*6+2];
        s_p[t] = make_float4(x, y, z, THR_FAST - (x*x + y*y + z*z));
    }
    __syncthreads();

    // ---- main loop: 2 rows in flight (g selects), STG.64 per row ----
    float2* base2 = (float2*)(out + ((size_t)b * QQ + q0) * NN);

    #pragma unroll 4
    for (int k = 0; k < QT / 2; k++) {
        const int r = 2 * k + g;                        // warp-uniform row
        const float4 p = s_p[r];                        // broadcast LDS.128
        const float m0 = fmaf(Ax0, p.x, fmaf(Ay0, p.y, fmaf(Az0, p.z, K0)));
        const float m1 = fmaf(Ax1, p.x, fmaf(Ay1, p.y, fmaf(Az1, p.z, K1)));
        const bool near = (fminf(m0, m1) <= p.w);       // FMNMX + FSETP

        float2 v = make_float2(INF_REPLACE, INF_REPLACE);
        if (__any_sync(0xFFFFFFFFu, near)) {            // warp-uniform, rare
            if (near) {
                // exact decisions (reference arithmetic) for both targets
                {
                    const float dx = p.x - tx0, dy = p.y - ty0, dz = p.z - tz0;
                    const float dist = sqrtf(dx*dx + dy*dy + dz*dz);
                    if (dist <= 2.0f)
                        v.x = exact_cost(logits, labels, tboxes,
                                         b, q0 + r, n0, p.x, p.y, p.z, dist, pboxes);
                }
                {
                    const float dx = p.x - tx1, dy = p.y - ty1, dz = p.z - tz1;
                    const float dist = sqrtf(dx*dx + dy*dy + dz*dz);
                    if (dist <= 2.0f)
                        v.y = exact_cost(logits, labels, tboxes,
                                         b, q0 + r, n1, p.x, p.y, p.z, dist, pboxes);
                }
            }
        }
        base2[(size_t)r * 128 + u] = v;                 // 8B per thread, coalesced
    }
}

extern "C" void kernel_launch(void* const* d_in, const int* in_sizes, int n_in,
                              void* d_out, int out_size)
{
    const float* logits = (const float*)d_in[0];  // [B,Q,21]
    const float* pboxes = (const float*)d_in[1];  // [B,Q,6]
    const int*   labels = (const int*)  d_in[2];  // [B,N]
    const float* tboxes = (const float*)d_in[3];  // [B,N,6]
    float*       out    = (float*)d_out;          // [B,Q,N]

    dim3 grid(QQ / QT, BB);                       // (32, 64) = 2048 blocks
    matcher_kernel<<<grid, 256>>>(logits, pboxes, labels, tboxes, out);
}

// round 15
// speedup vs baseline: 2.5931x; 1.0431x over previous
#include <cuda_runtime.h>
#include <math.h>

#define BB 64
#define QQ 4096
#define NN 256
#define NL 21
#define QT  128                  // q rows per block
#define INF_REPLACE 1000000.0f
// Conservative gate on expanded d^2 = |p|^2 - 2 p.t + |t|^2 (fp32 magnitudes
// <= ~1.5e4 -> rounding error << 1/16). Every pair with true d^2 <= 4 passes;
// gated-in pairs are decided by the exact reference computation
// (dist = sqrt(sum((p-t)^2)) <= 2), so boundary decisions match the reference.
#define THR_FAST 4.0625f

// ---------------- exact cost (reference arithmetic, rare) -------------------
__device__ __noinline__ float exact_cost(
    const float* __restrict__ logits, const int* __restrict__ labels,
    const float* __restrict__ tboxes,
    int b, int q, int n,
    float pcx, float pcy, float pcz, float dist,
    const float* __restrict__ pboxes)
{
    const float* pb = pboxes + ((size_t)b * QQ + q) * 6;
    const float psx = __ldg(pb + 3), psy = __ldg(pb + 4), psz = __ldg(pb + 5);

    const float* tb = tboxes + ((size_t)b * NN + n) * 6;
    const float tcx = __ldg(tb + 0), tcy = __ldg(tb + 1), tcz = __ldg(tb + 2);
    const float tsx = __ldg(tb + 3), tsy = __ldg(tb + 4), tsz = __ldg(tb + 5);

    float ix = fminf(pcx + 0.5f*psx, tcx + 0.5f*tsx) - fmaxf(pcx - 0.5f*psx, tcx - 0.5f*tsx);
    float iy = fminf(pcy + 0.5f*psy, tcy + 0.5f*tsy) - fmaxf(pcy - 0.5f*psy, tcy - 0.5f*tsy);
    float iz = fminf(pcz + 0.5f*psz, tcz + 0.5f*tsz) - fmaxf(pcz - 0.5f*psz, tcz - 0.5f*tsz);
    ix = fmaxf(ix, 0.0f); iy = fmaxf(iy, 0.0f); iz = fmaxf(iz, 0.0f);

    const float inter = ix * iy * iz;
    const float vol1 = psx * psy * psz;
    const float vol2 = tsx * tsy * tsz;
    const float uni  = vol1 + vol2 - inter;
    const float iou  = (uni > 0.0f) ? (inter / uni) : 0.0f;

    const float* lg = logits + ((size_t)b * QQ + q) * NL;
    const int lbl = __ldg(labels + b * NN + n);
    float s = 0.0f, el = 0.0f;
    #pragma unroll
    for (int c = 0; c < NL; c++) {
        const float e = expf(__ldg(lg + c));
        s += e;
        if (c == lbl) el = e;
    }
    const float cls = -(el / s);
    return cls + 5.0f * dist + 2.0f * (1.0f - iou);
}

// ---------------- single fused kernel ---------------------------------------
__global__ __launch_bounds__(256) void matcher_kernel(
    const float* __restrict__ logits,    // [B, Q, 21]
    const float* __restrict__ pboxes,    // [B, Q, 6]
    const int*   __restrict__ labels,    // [B, N]
    const float* __restrict__ tboxes,    // [B, N, 6]
    float*       __restrict__ out)       // [B, Q, N]
{
    const int b  = blockIdx.y;
    const int q0 = blockIdx.x * QT;
    const int t  = threadIdx.x;
    const int g  = t >> 6;               // 0..3 — row offset (warp-uniform)
    const int u  = t & 63;               // owns targets 4u .. 4u+3

    __shared__ float  s_praw[QT * 6];    // staged pred boxes (raw)
    __shared__ float  s_traw[NN * 6];    // staged target boxes (raw)
    __shared__ float4 s_p[QT];           // (px, py, pz, tq = THR - |p|^2)

    // ---- coalesced staging ----
    {
        const float* pb = pboxes + ((size_t)b * QQ + q0) * 6;
        #pragma unroll
        for (int i = t; i < QT * 6; i += 256) s_praw[i] = pb[i];
        const float* tb = tboxes + (size_t)b * NN * 6;
        #pragma unroll
        for (int i = t; i < NN * 6; i += 256) s_traw[i] = tb[i];
    }
    __syncthreads();

    // per-thread gate constants for the four owned targets (registers only)
    float Ax[4], Ay[4], Az[4], K[4];
    #pragma unroll
    for (int j = 0; j < 4; j++) {
        const int n = 4 * u + j;
        const float x = s_traw[n*6+0], y = s_traw[n*6+1], z = s_traw[n*6+2];
        Ax[j] = -2.0f*x; Ay[j] = -2.0f*y; Az[j] = -2.0f*z;
        K[j]  = x*x + y*y + z*z;
    }

    // per-row broadcast constants
    if (t < QT) {
        const float x = s_praw[t*6+0], y = s_praw[t*6+1], z = s_praw[t*6+2];
        s_p[t] = make_float4(x, y, z, THR_FAST - (x*x + y*y + z*z));
    }
    __syncthreads();

    // ---- main loop: 4 rows in flight (g selects), STG.128 per row ----
    float4* base4 = (float4*)(out + ((size_t)b * QQ + q0) * NN);

    #pragma unroll 4
    for (int k = 0; k < QT / 4; k++) {
        const int r = 4 * k + g;                        // warp-uniform row
        const float4 p = s_p[r];                        // broadcast LDS.128
        const float m0 = fmaf(Ax[0], p.x, fmaf(Ay[0], p.y, fmaf(Az[0], p.z, K[0])));
        const float m1 = fmaf(Ax[1], p.x, fmaf(Ay[1], p.y, fmaf(Az[1], p.z, K[1])));
        const float m2 = fmaf(Ax[2], p.x, fmaf(Ay[2], p.y, fmaf(Az[2], p.z, K[2])));
        const float m3 = fmaf(Ax[3], p.x, fmaf(Ay[3], p.y, fmaf(Az[3], p.z, K[3])));
        const float mmin = fminf(fminf(m0, m1), fminf(m2, m3));
        const bool near = (mmin <= p.w);

        float4 v = make_float4(INF_REPLACE, INF_REPLACE, INF_REPLACE, INF_REPLACE);
        if (__any_sync(0xFFFFFFFFu, near)) {            // warp-uniform, rare
            if (near) {
                const float mm[4] = {m0, m1, m2, m3};
                float rv[4] = {INF_REPLACE, INF_REPLACE, INF_REPLACE, INF_REPLACE};
                #pragma unroll
                for (int j = 0; j < 4; j++) {
                    if (mm[j] <= p.w) {
                        // exact decision (reference arithmetic)
                        const float tx = -0.5f * Ax[j];
                        const float ty = -0.5f * Ay[j];
                        const float tz = -0.5f * Az[j];
                        const float dx = p.x - tx, dy = p.y - ty, dz = p.z - tz;
                        const float dist = sqrtf(dx*dx + dy*dy + dz*dz);
                        if (dist <= 2.0f)
                            rv[j] = exact_cost(logits, labels, tboxes,
                                               b, q0 + r, 4*u + j,
                                               p.x, p.y, p.z, dist, pboxes);
                    }
                }
                v = make_float4(rv[0], rv[1], rv[2], rv[3]);
            }
        }
        base4[(size_t)r * 64 + u] = v;                  // 16B per thread, coalesced
    }
}

extern "C" void kernel_launch(void* const* d_in, const int* in_sizes, int n_in,
                              void* d_out, int out_size)
{
    const float* logits = (const float*)d_in[0];  // [B,Q,21]
    const float* pboxes = (const float*)d_in[1];  // [B,Q,6]
    const int*   labels = (const int*)  d_in[2];  // [B,N]
    const float* tboxes = (const float*)d_in[3];  // [B,N,6]
    float*       out    = (float*)d_out;          // [B,Q,N]

    dim3 grid(QQ / QT, BB);                       // (32, 64) = 2048 blocks
    matcher_kernel<<<grid, 256>>>(logits, pboxes, labels, tboxes, out);
}